// round 3
// baseline (speedup 1.0000x reference)
#include <cuda_runtime.h>

#define IMG    512
#define OUTD   502
#define NIMG   96
#define TILE_W 126
#define VCOLS  136
#define TILE_H 16
#define GBX    4
#define GBY    32
#define NBLK   (GBX * GBY * NIMG)   // 12288
#define SROW   152                   // row stride in elements; 152 % 16 == 8 (bank skew)

// Gaussian(sigma=1.5, K=11) normalized weights
#define W0 0.00102839f
#define W1 0.00759864f
#define W2 0.03600077f
#define W3 0.10936070f
#define W4 0.21300553f
#define W5 0.26601172f

__device__ int      g_flags[2] = {0, 0};
__device__ unsigned g_count    = 0u;
__device__ float    g_partials[NBLK];

// any(img1 > 128), any(img1 < -0.5)
__global__ void k_flags(const float4* __restrict__ x, int n4) {
    bool f1 = false, f2 = false;
    for (int i = blockIdx.x * blockDim.x + threadIdx.x; i < n4; i += gridDim.x * blockDim.x) {
        float4 v = x[i];
        f1 |= (v.x > 128.0f) | (v.y > 128.0f) | (v.z > 128.0f) | (v.w > 128.0f);
        f2 |= (v.x < -0.5f) | (v.y < -0.5f) | (v.z < -0.5f) | (v.w < -0.5f);
    }
    unsigned m1 = __ballot_sync(0xffffffffu, f1);
    unsigned m2 = __ballot_sync(0xffffffffu, f2);
    if ((threadIdx.x & 31) == 0) {
        if (m1) atomicOr(&g_flags[0], 1);
        if (m2) atomicOr(&g_flags[1], 1);
    }
}

__global__ __launch_bounds__(128)
void k_ssim(const float* __restrict__ img1, const float* __restrict__ img2,
            float* __restrict__ out) {
    __shared__ float2 s01[TILE_H][SROW];   // (vconv of img1, img2)
    __shared__ float2 s23[TILE_H][SROW];   // (vconv of img1^2, img2^2)
    __shared__ float  s4 [TILE_H][SROW];   // vconv of img1*img2
    __shared__ float  warpsum[4];
    __shared__ int    s_last;
    __shared__ double red[4];

    // weights as compile-time literals -> FFMA-imm (rt=1) after const-prop
    const float W[11] = {W0, W1, W2, W3, W4, W5, W4, W3, W2, W1, W0};

    const int tid = threadIdx.x;
    const int bx = blockIdx.x, by = blockIdx.y, z = blockIdx.z;
    const float* p1 = img1 + (size_t)z * IMG * IMG;
    const float* p2 = img2 + (size_t)z * IMG * IMG;
    const int ybase = by * TILE_H;

    // ---------------- Phase 1: vertical 11-tap conv (scalar sliding accumulators) ------------
    // 136 vconv columns, 128 threads: threads 0..7 handle a second column (128+tid).
#pragma unroll 1
    for (int cc = 0; cc < 2; cc++) {
        if (cc == 1 && tid >= VCOLS - 128) break;
        const int c  = (cc == 0) ? tid : 128 + tid;
        const int gx = bx * TILE_W + c;
        const bool colok = (gx < IMG);

        float a0[TILE_H], a1[TILE_H], a2[TILE_H], a3[TILE_H], a4[TILE_H];
#pragma unroll
        for (int r = 0; r < TILE_H; r++) { a0[r]=0.f; a1[r]=0.f; a2[r]=0.f; a3[r]=0.f; a4[r]=0.f; }

#pragma unroll
        for (int j = 0; j < TILE_H + 10; j++) {
            const int yin = ybase + j;
            float a = 0.0f, b = 0.0f;
            if (colok && yin < IMG) {
                a = p1[yin * IMG + gx];
                b = p2[yin * IMG + gx];
            }
            const float aa = a * a, bb = b * b, ab = a * b;
#pragma unroll
            for (int r = 0; r < TILE_H; r++) {
                const int k = j - r;
                if (k >= 0 && k < 11) {
                    a0[r] = fmaf(W[k], a,  a0[r]);
                    a1[r] = fmaf(W[k], b,  a1[r]);
                    a2[r] = fmaf(W[k], aa, a2[r]);
                    a3[r] = fmaf(W[k], bb, a3[r]);
                    a4[r] = fmaf(W[k], ab, a4[r]);
                }
            }
        }

        const int ph = c + (c >> 4);   // skewed physical column
#pragma unroll
        for (int r = 0; r < TILE_H; r++) {
            s01[r][ph] = make_float2(a0[r], a1[r]);
            s23[r][ph] = make_float2(a2[r], a3[r]);
            s4 [r][ph] = a4[r];
        }
    }
    __syncthreads();

    // ---------------- Phase 2: horizontal 11-tap conv (scalar sliding window) ------------
    const int y  = tid >> 3;      // 0..15 output row
    const int cg = tid & 7;       // 0..7  column group of 16 outputs
    const int pbase = cg * 17;    // phys base = phys(cg*16)

    float o0[16], o1[16], o2[16], o3[16], o4[16];
#pragma unroll
    for (int s = 0; s < 16; s++) { o0[s]=0.f; o1[s]=0.f; o2[s]=0.f; o3[s]=0.f; o4[s]=0.f; }

    {
        const float2* r01 = &s01[y][pbase];
#pragma unroll
        for (int i = 0; i < 26; i++) {
            const float2 v = r01[i + (i >> 4)];
#pragma unroll
            for (int s = 0; s < 16; s++) {
                const int k = i - s;
                if (k >= 0 && k < 11) {
                    o0[s] = fmaf(W[k], v.x, o0[s]);
                    o1[s] = fmaf(W[k], v.y, o1[s]);
                }
            }
        }
    }
    {
        const float2* r23 = &s23[y][pbase];
#pragma unroll
        for (int i = 0; i < 26; i++) {
            const float2 v = r23[i + (i >> 4)];
#pragma unroll
            for (int s = 0; s < 16; s++) {
                const int k = i - s;
                if (k >= 0 && k < 11) {
                    o2[s] = fmaf(W[k], v.x, o2[s]);
                    o3[s] = fmaf(W[k], v.y, o3[s]);
                }
            }
        }
    }
    {
        const float* r4 = &s4[y][pbase];
#pragma unroll
        for (int i = 0; i < 26; i++) {
            const float v = r4[i + (i >> 4)];
#pragma unroll
            for (int s = 0; s < 16; s++) {
                const int k = i - s;
                if (k >= 0 && k < 11) o4[s] = fmaf(W[k], v, o4[s]);
            }
        }
    }

    // ---------------- SSIM map + block-local sum ----------------
    const float maxv = g_flags[0] ? 255.0f : 1.0f;
    const float minv = g_flags[1] ? -1.0f : 0.0f;
    const float L  = maxv - minv;
    const float C1 = (0.01f * L) * (0.01f * L);
    const float C2 = (0.03f * L) * (0.03f * L);

    const int gy   = ybase + y;
    const int xlim = min(TILE_W, OUTD - bx * TILE_W);

    float lsum = 0.0f;
    if (gy < OUTD) {
#pragma unroll
        for (int s = 0; s < 16; s++) {
            const int x = cg * 16 + s;
            if (x < xlim) {
                const float mu1 = o0[s], mu2 = o1[s];
                const float mu1s = mu1 * mu1, mu2s = mu2 * mu2, mu12 = mu1 * mu2;
                const float s1  = o2[s] - mu1s;
                const float s2  = o3[s] - mu2s;
                const float s12 = o4[s] - mu12;
                const float num = (2.0f * mu12 + C1) * (2.0f * s12 + C2);
                const float den = (mu1s + mu2s + C1) * (s1 + s2 + C2);
                lsum += __fdividef(num, den);
            }
        }
    }

#pragma unroll
    for (int off = 16; off > 0; off >>= 1)
        lsum += __shfl_down_sync(0xffffffffu, lsum, off);

    if ((tid & 31) == 0) warpsum[tid >> 5] = lsum;
    __syncthreads();

    const int bid = bx + GBX * (by + GBY * z);
    if (tid == 0) {
        g_partials[bid] = warpsum[0] + warpsum[1] + warpsum[2] + warpsum[3];
        __threadfence();
        unsigned v = atomicAdd(&g_count, 1u);
        s_last = (v == NBLK - 1) ? 1 : 0;
    }
    __syncthreads();

    // ---------------- last block: final reduction + state reset for next replay ----------
    if (s_last) {
        double s = 0.0;
        const int per = NBLK / 128;  // 96
#pragma unroll 4
        for (int i = 0; i < per; i++)
            s += (double)__ldcg(&g_partials[tid * per + i]);
#pragma unroll
        for (int off = 16; off > 0; off >>= 1)
            s += __shfl_down_sync(0xffffffffu, s, off);
        if ((tid & 31) == 0) red[tid >> 5] = s;
        __syncthreads();
        if (tid == 0) {
            const double cnt = (double)NIMG * OUTD * OUTD;
            out[0] = (float)(1.0 - (red[0] + red[1] + red[2] + red[3]) / cnt);
            // reset device state so the next graph replay starts clean
            g_flags[0] = 0;
            g_flags[1] = 0;
            g_count    = 0u;
        }
    }
}

extern "C" void kernel_launch(void* const* d_in, const int* in_sizes, int n_in,
                              void* d_out, int out_size) {
    const float* img1 = (const float*)d_in[0];
    const float* img2 = (const float*)d_in[1];
    float* out = (float*)d_out;

    k_flags<<<2048, 256>>>((const float4*)img1, (IMG * IMG * NIMG) / 4);
    dim3 grid(GBX, GBY, NIMG);
    k_ssim<<<grid, 128>>>(img1, img2, out);
}

// round 4
// speedup vs baseline: 1.0233x; 1.0233x over previous
#include <cuda_runtime.h>

#define IMG    512
#define OUTD   502
#define NIMG   96
#define TILE_W 118
#define TILE_H 16
#define GBX    5
#define GBY    32
#define NBLK   (GBX * GBY * NIMG)   // 15360
#define SROW   136                   // smem row stride (elements); bank-conflict-free, see analysis

// Gaussian(sigma=1.5, K=11) normalized weights
#define W0 0.00102839f
#define W1 0.00759864f
#define W2 0.03600077f
#define W3 0.10936070f
#define W4 0.21300553f
#define W5 0.26601172f

__device__ int      g_flags[2] = {0, 0};
__device__ unsigned g_count    = 0u;
__device__ float    g_partials[NBLK];

// any(img1 > 128), any(img1 < -0.5)
__global__ void k_flags(const float4* __restrict__ x, int n4) {
    bool f1 = false, f2 = false;
    for (int i = blockIdx.x * blockDim.x + threadIdx.x; i < n4; i += gridDim.x * blockDim.x) {
        float4 v = x[i];
        f1 |= (v.x > 128.0f) | (v.y > 128.0f) | (v.z > 128.0f) | (v.w > 128.0f);
        f2 |= (v.x < -0.5f) | (v.y < -0.5f) | (v.z < -0.5f) | (v.w < -0.5f);
    }
    unsigned m1 = __ballot_sync(0xffffffffu, f1);
    unsigned m2 = __ballot_sync(0xffffffffu, f2);
    if ((threadIdx.x & 31) == 0) {
        if (m1) atomicOr(&g_flags[0], 1);
        if (m2) atomicOr(&g_flags[1], 1);
    }
}

__global__ __launch_bounds__(128)
void k_ssim(const float* __restrict__ img1, const float* __restrict__ img2,
            float* __restrict__ out) {
    __shared__ float2 s01[TILE_H][SROW];   // (vconv img1, vconv img2)
    __shared__ float2 s23[TILE_H][SROW];   // (vconv img1^2, vconv img2^2)
    __shared__ float  s4 [TILE_H][SROW];   // vconv img1*img2
    __shared__ float  warpsum[4];
    __shared__ int    s_last;
    __shared__ double red[4];

    // compile-time literal weights -> FFMA with immediate multiplier (rt_SMSP = 1)
    const float W[11] = {W0, W1, W2, W3, W4, W5, W4, W3, W2, W1, W0};

    const int tid = threadIdx.x;
    const int bx = blockIdx.x, by = blockIdx.y, z = blockIdx.z;
    const float* p1 = img1 + (size_t)z * IMG * IMG;
    const float* p2 = img2 + (size_t)z * IMG * IMG;
    const int ybase = by * TILE_H;

    // ---------------- Phase 1: vertical 11-tap conv, one column per thread ----------------
    const int gx = bx * TILE_W + tid;
    const bool colok = (gx < IMG);

    float a0[TILE_H], a1[TILE_H], a2[TILE_H], a3[TILE_H], a4[TILE_H];
#pragma unroll
    for (int r = 0; r < TILE_H; r++) { a0[r]=0.f; a1[r]=0.f; a2[r]=0.f; a3[r]=0.f; a4[r]=0.f; }

#pragma unroll
    for (int j = 0; j < TILE_H + 10; j++) {
        const int yin = ybase + j;
        float a = 0.0f, b = 0.0f;
        if (colok && yin < IMG) {
            a = p1[yin * IMG + gx];
            b = p2[yin * IMG + gx];
        }
        const float aa = a * a, bb = b * b, ab = a * b;
#pragma unroll
        for (int r = 0; r < TILE_H; r++) {
            const int k = j - r;
            if (k >= 0 && k < 11) {
                a0[r] = fmaf(W[k], a,  a0[r]);
                a1[r] = fmaf(W[k], b,  a1[r]);
                a2[r] = fmaf(W[k], aa, a2[r]);
                a3[r] = fmaf(W[k], bb, a3[r]);
                a4[r] = fmaf(W[k], ab, a4[r]);
            }
        }
    }

#pragma unroll
    for (int r = 0; r < TILE_H; r++) {
        s01[r][tid] = make_float2(a0[r], a1[r]);
        s23[r][tid] = make_float2(a2[r], a3[r]);
        s4 [r][tid] = a4[r];
    }
    __syncthreads();

    // ---------------- Phase 2: horizontal 11-tap conv, 15 outputs per thread ----------------
    const int y  = tid >> 3;      // 0..15 output row
    const int cg = tid & 7;       // 0..7  column group
    const int xs = cg * 15;       // local out cols xs..xs+14

    float o0[15], o1[15], o2[15], o3[15], o4[15];
#pragma unroll
    for (int s = 0; s < 15; s++) { o0[s]=0.f; o1[s]=0.f; o2[s]=0.f; o3[s]=0.f; o4[s]=0.f; }

    {
        const float2* r01 = &s01[y][xs];
#pragma unroll
        for (int i = 0; i < 25; i++) {
            const float2 v = r01[i];   // cols up to 129 < 136; cols 128/129 feed masked outputs only
#pragma unroll
            for (int s = 0; s < 15; s++) {
                const int k = i - s;
                if (k >= 0 && k < 11) {
                    o0[s] = fmaf(W[k], v.x, o0[s]);
                    o1[s] = fmaf(W[k], v.y, o1[s]);
                }
            }
        }
    }
    {
        const float2* r23 = &s23[y][xs];
#pragma unroll
        for (int i = 0; i < 25; i++) {
            const float2 v = r23[i];
#pragma unroll
            for (int s = 0; s < 15; s++) {
                const int k = i - s;
                if (k >= 0 && k < 11) {
                    o2[s] = fmaf(W[k], v.x, o2[s]);
                    o3[s] = fmaf(W[k], v.y, o3[s]);
                }
            }
        }
    }
    {
        const float* r4 = &s4[y][xs];
#pragma unroll
        for (int i = 0; i < 25; i++) {
            const float v = r4[i];
#pragma unroll
            for (int s = 0; s < 15; s++) {
                const int k = i - s;
                if (k >= 0 && k < 11) o4[s] = fmaf(W[k], v, o4[s]);
            }
        }
    }

    // ---------------- SSIM map + block-local sum ----------------
    const float maxv = g_flags[0] ? 255.0f : 1.0f;
    const float minv = g_flags[1] ? -1.0f : 0.0f;
    const float L  = maxv - minv;
    const float C1 = (0.01f * L) * (0.01f * L);
    const float C2 = (0.03f * L) * (0.03f * L);

    const int gy   = ybase + y;
    const int xlim = min(TILE_W, OUTD - bx * TILE_W);

    float lsum = 0.0f;
    if (gy < OUTD) {
#pragma unroll
        for (int s = 0; s < 15; s++) {
            const int x = xs + s;
            if (x < xlim) {
                const float mu1 = o0[s], mu2 = o1[s];
                const float mu1s = mu1 * mu1, mu2s = mu2 * mu2, mu12 = mu1 * mu2;
                const float s1  = o2[s] - mu1s;
                const float s2  = o3[s] - mu2s;
                const float s12 = o4[s] - mu12;
                const float num = (2.0f * mu12 + C1) * (2.0f * s12 + C2);
                const float den = (mu1s + mu2s + C1) * (s1 + s2 + C2);
                lsum += __fdividef(num, den);
            }
        }
    }

#pragma unroll
    for (int off = 16; off > 0; off >>= 1)
        lsum += __shfl_down_sync(0xffffffffu, lsum, off);

    if ((tid & 31) == 0) warpsum[tid >> 5] = lsum;
    __syncthreads();

    const int bid = bx + GBX * (by + GBY * z);
    if (tid == 0) {
        g_partials[bid] = warpsum[0] + warpsum[1] + warpsum[2] + warpsum[3];
        __threadfence();
        unsigned v = atomicAdd(&g_count, 1u);
        s_last = (v == NBLK - 1) ? 1 : 0;
    }
    __syncthreads();

    // ---------------- last block: final reduction + state reset for next replay ----------
    if (s_last) {
        double s = 0.0;
        const int per = NBLK / 128;  // 120
#pragma unroll 4
        for (int i = 0; i < per; i++)
            s += (double)__ldcg(&g_partials[tid * per + i]);
#pragma unroll
        for (int off = 16; off > 0; off >>= 1)
            s += __shfl_down_sync(0xffffffffu, s, off);
        if ((tid & 31) == 0) red[tid >> 5] = s;
        __syncthreads();
        if (tid == 0) {
            const double cnt = (double)NIMG * OUTD * OUTD;
            out[0] = (float)(1.0 - (red[0] + red[1] + red[2] + red[3]) / cnt);
            g_flags[0] = 0;
            g_flags[1] = 0;
            g_count    = 0u;
        }
    }
}

extern "C" void kernel_launch(void* const* d_in, const int* in_sizes, int n_in,
                              void* d_out, int out_size) {
    const float* img1 = (const float*)d_in[0];
    const float* img2 = (const float*)d_in[1];
    float* out = (float*)d_out;

    k_flags<<<2048, 256>>>((const float4*)img1, (IMG * IMG * NIMG) / 4);
    dim3 grid(GBX, GBY, NIMG);
    k_ssim<<<grid, 128>>>(img1, img2, out);
}

// round 5
// speedup vs baseline: 1.1283x; 1.1026x over previous
#include <cuda_runtime.h>

#define IMG    512
#define OUTD   502
#define NIMG   96
#define TILE_W 118
#define TILE_H 16
#define GBX    5
#define GBY    32
#define NBLK   (GBX * GBY * NIMG)   // 15360
#define SROW   136

// Gaussian(sigma=1.5, K=11) normalized weights
#define W0 0.00102839f
#define W1 0.00759864f
#define W2 0.03600077f
#define W3 0.10936070f
#define W4 0.21300553f
#define W5 0.26601172f

typedef unsigned long long u64;

// ---- packed f32x2 helpers (sm_100+) ----
#define PACK2(out, lo, hi) asm("mov.b64 %0, {%1, %2};" : "=l"(out) : "f"(lo), "f"(hi))
#define UNPACK2(lo, hi, in) asm("mov.b64 {%0, %1}, %2;" : "=f"(lo), "=f"(hi) : "l"(in))
#define FMA2(d, a, b, c) asm("fma.rn.f32x2 %0, %1, %2, %3;" : "=l"(d) : "l"(a), "l"(b), "l"(c))
#define MUL2(d, a, b)    asm("mul.rn.f32x2 %0, %1, %2;" : "=l"(d) : "l"(a), "l"(b))

__device__ int      g_flags[2] = {0, 0};
__device__ unsigned g_count    = 0u;
__device__ float    g_partials[NBLK];

// any(img1 > 128), any(img1 < -0.5)
__global__ void k_flags(const float4* __restrict__ x, int n4) {
    bool f1 = false, f2 = false;
    for (int i = blockIdx.x * blockDim.x + threadIdx.x; i < n4; i += gridDim.x * blockDim.x) {
        float4 v = x[i];
        f1 |= (v.x > 128.0f) | (v.y > 128.0f) | (v.z > 128.0f) | (v.w > 128.0f);
        f2 |= (v.x < -0.5f) | (v.y < -0.5f) | (v.z < -0.5f) | (v.w < -0.5f);
    }
    unsigned m1 = __ballot_sync(0xffffffffu, f1);
    unsigned m2 = __ballot_sync(0xffffffffu, f2);
    if ((threadIdx.x & 31) == 0) {
        if (m1) atomicOr(&g_flags[0], 1);
        if (m2) atomicOr(&g_flags[1], 1);
    }
}

__global__ __launch_bounds__(128, 5)
void k_ssim(const float* __restrict__ img1, const float* __restrict__ img2,
            float* __restrict__ out) {
    __shared__ u64   s01[TILE_H][SROW];   // packed (vconv img1, vconv img2)
    __shared__ u64   s23[TILE_H][SROW];   // packed (vconv img1^2, vconv img2^2)
    __shared__ float s4 [TILE_H][SROW];   // vconv img1*img2
    __shared__ float warpsum[4];
    __shared__ int   s_last;
    __shared__ double red[4];

    // scalar weights as literals (FFMA-imm, rt=1)
    const float Wf[11] = {W0, W1, W2, W3, W4, W5, W4, W3, W2, W1, W0};
    // packed weights: only 6 distinct by symmetry (12 regs, not 22)
    u64 w2[6];
    {
        const float wv[6] = {W0, W1, W2, W3, W4, W5};
#pragma unroll
        for (int k = 0; k < 6; k++) PACK2(w2[k], wv[k], wv[k]);
    }
#define WIDX(k) ((k) < 6 ? (k) : 10 - (k))

    const int tid = threadIdx.x;
    const int bx = blockIdx.x, by = blockIdx.y, z = blockIdx.z;
    const float* p1 = img1 + (size_t)z * IMG * IMG;
    const float* p2 = img2 + (size_t)z * IMG * IMG;
    const int ybase = by * TILE_H;

    // ---------------- Phase 1: vertical 11-tap conv, packed sliding accumulators ----------
    const int gx = bx * TILE_W + tid;
    const bool colok = (gx < IMG);

    u64 acc01[TILE_H], acc23[TILE_H];
    float acc4[TILE_H];
#pragma unroll
    for (int r = 0; r < TILE_H; r++) { acc01[r] = 0ull; acc23[r] = 0ull; acc4[r] = 0.0f; }

#pragma unroll
    for (int j = 0; j < TILE_H + 10; j++) {
        const int yin = ybase + j;
        float a = 0.0f, b = 0.0f;
        if (colok && yin < IMG) {
            a = p1[yin * IMG + gx];
            b = p2[yin * IMG + gx];
        }
        u64 vab, vsq;
        PACK2(vab, a, b);
        MUL2(vsq, vab, vab);
        const float ab = a * b;
#pragma unroll
        for (int r = 0; r < TILE_H; r++) {
            const int k = j - r;
            if (k >= 0 && k < 11) {
                FMA2(acc01[r], vab, w2[WIDX(k)], acc01[r]);
                FMA2(acc23[r], vsq, w2[WIDX(k)], acc23[r]);
                acc4[r] = fmaf(Wf[k], ab, acc4[r]);
            }
        }
    }

#pragma unroll
    for (int r = 0; r < TILE_H; r++) {
        s01[r][tid] = acc01[r];
        s23[r][tid] = acc23[r];
        s4 [r][tid] = acc4[r];
    }
    __syncthreads();

    // ---------------- Phase 2: horizontal 11-tap conv, packed, inline loads --------------
    const int y  = tid >> 3;      // 0..15 output row
    const int cg = tid & 7;       // 0..7  column group
    const int xs = cg * 15;       // local out cols xs..xs+14 (xs+24 <= 129 < 136)

    u64 o01[15], o23[15];
    float o4[15];
#pragma unroll
    for (int s = 0; s < 15; s++) { o01[s] = 0ull; o23[s] = 0ull; o4[s] = 0.0f; }

    {
        const u64* r01 = &s01[y][xs];
#pragma unroll
        for (int i = 0; i < 25; i++) {
            const u64 v = r01[i];
#pragma unroll
            for (int s = 0; s < 15; s++) {
                const int k = i - s;
                if (k >= 0 && k < 11) FMA2(o01[s], v, w2[WIDX(k)], o01[s]);
            }
        }
    }
    {
        const u64* r23 = &s23[y][xs];
#pragma unroll
        for (int i = 0; i < 25; i++) {
            const u64 v = r23[i];
#pragma unroll
            for (int s = 0; s < 15; s++) {
                const int k = i - s;
                if (k >= 0 && k < 11) FMA2(o23[s], v, w2[WIDX(k)], o23[s]);
            }
        }
    }
    {
        const float* r4 = &s4[y][xs];
#pragma unroll
        for (int i = 0; i < 25; i++) {
            const float v = r4[i];
#pragma unroll
            for (int s = 0; s < 15; s++) {
                const int k = i - s;
                if (k >= 0 && k < 11) o4[s] = fmaf(Wf[k], v, o4[s]);
            }
        }
    }

    // ---------------- SSIM map + block-local sum ----------------
    const float maxv = g_flags[0] ? 255.0f : 1.0f;
    const float minv = g_flags[1] ? -1.0f : 0.0f;
    const float L  = maxv - minv;
    const float C1 = (0.01f * L) * (0.01f * L);
    const float C2 = (0.03f * L) * (0.03f * L);

    const int gy   = ybase + y;
    const int xlim = min(TILE_W, OUTD - bx * TILE_W);

    float lsum = 0.0f;
    if (gy < OUTD) {
#pragma unroll
        for (int s = 0; s < 15; s++) {
            const int x = xs + s;
            if (x < xlim) {
                float mu1, mu2, e11, e22;
                UNPACK2(mu1, mu2, o01[s]);
                UNPACK2(e11, e22, o23[s]);
                const float mu1s = mu1 * mu1, mu2s = mu2 * mu2, mu12 = mu1 * mu2;
                const float s1  = e11 - mu1s;
                const float s2  = e22 - mu2s;
                const float s12 = o4[s] - mu12;
                const float num = (2.0f * mu12 + C1) * (2.0f * s12 + C2);
                const float den = (mu1s + mu2s + C1) * (s1 + s2 + C2);
                lsum += __fdividef(num, den);
            }
        }
    }

#pragma unroll
    for (int off = 16; off > 0; off >>= 1)
        lsum += __shfl_down_sync(0xffffffffu, lsum, off);

    if ((tid & 31) == 0) warpsum[tid >> 5] = lsum;
    __syncthreads();

    const int bid = bx + GBX * (by + GBY * z);
    if (tid == 0) {
        g_partials[bid] = warpsum[0] + warpsum[1] + warpsum[2] + warpsum[3];
        __threadfence();
        unsigned v = atomicAdd(&g_count, 1u);
        s_last = (v == NBLK - 1) ? 1 : 0;
    }
    __syncthreads();

    // ---------------- last block: final reduction + state reset ----------------
    if (s_last) {
        double s = 0.0;
        const int per = NBLK / 128;  // 120
#pragma unroll 4
        for (int i = 0; i < per; i++)
            s += (double)__ldcg(&g_partials[tid * per + i]);
#pragma unroll
        for (int off = 16; off > 0; off >>= 1)
            s += __shfl_down_sync(0xffffffffu, s, off);
        if ((tid & 31) == 0) red[tid >> 5] = s;
        __syncthreads();
        if (tid == 0) {
            const double cnt = (double)NIMG * OUTD * OUTD;
            out[0] = (float)(1.0 - (red[0] + red[1] + red[2] + red[3]) / cnt);
            g_flags[0] = 0;
            g_flags[1] = 0;
            g_count    = 0u;
        }
    }
}

extern "C" void kernel_launch(void* const* d_in, const int* in_sizes, int n_in,
                              void* d_out, int out_size) {
    const float* img1 = (const float*)d_in[0];
    const float* img2 = (const float*)d_in[1];
    float* out = (float*)d_out;

    k_flags<<<2048, 256>>>((const float4*)img1, (IMG * IMG * NIMG) / 4);
    dim3 grid(GBX, GBY, NIMG);
    k_ssim<<<grid, 128>>>(img1, img2, out);
}

// round 6
// speedup vs baseline: 1.1556x; 1.0242x over previous
#include <cuda_runtime.h>

#define IMG    512
#define OUTD   502
#define NIMG   96
#define TILE_W 86
#define VCOLS  96
#define TILE_H 16
#define GBX    6
#define GBY    32
#define NBLK   (GBX * GBY * NIMG)   // 18432
#define SROW   99                    // smem row stride: bank-conflict-free (see analysis)
#define G      11                    // phase-2 outputs per thread

// Gaussian(sigma=1.5, K=11) normalized weights
#define W0 0.00102839f
#define W1 0.00759864f
#define W2 0.03600077f
#define W3 0.10936070f
#define W4 0.21300553f
#define W5 0.26601172f

typedef unsigned long long u64;

// ---- packed f32x2 helpers (sm_100+) ----
#define PACK2(out, lo, hi) asm("mov.b64 %0, {%1, %2};" : "=l"(out) : "f"(lo), "f"(hi))
#define UNPACK2(lo, hi, in) asm("mov.b64 {%0, %1}, %2;" : "=f"(lo), "=f"(hi) : "l"(in))
#define FMA2(d, a, b, c) asm("fma.rn.f32x2 %0, %1, %2, %3;" : "=l"(d) : "l"(a), "l"(b), "l"(c))
#define MUL2(d, a, b)    asm("mul.rn.f32x2 %0, %1, %2;" : "=l"(d) : "l"(a), "l"(b))

__device__ int      g_flags[2] = {0, 0};
__device__ unsigned g_count    = 0u;
__device__ float    g_partials[NBLK];

// any(img1 > 128), any(img1 < -0.5)
__global__ void k_flags(const float4* __restrict__ x, int n4) {
    bool f1 = false, f2 = false;
    for (int i = blockIdx.x * blockDim.x + threadIdx.x; i < n4; i += gridDim.x * blockDim.x) {
        float4 v = x[i];
        f1 |= (v.x > 128.0f) | (v.y > 128.0f) | (v.z > 128.0f) | (v.w > 128.0f);
        f2 |= (v.x < -0.5f) | (v.y < -0.5f) | (v.z < -0.5f) | (v.w < -0.5f);
    }
    unsigned m1 = __ballot_sync(0xffffffffu, f1);
    unsigned m2 = __ballot_sync(0xffffffffu, f2);
    if ((threadIdx.x & 31) == 0) {
        if (m1) atomicOr(&g_flags[0], 1);
        if (m2) atomicOr(&g_flags[1], 1);
    }
}

__global__ __launch_bounds__(128, 5)
void k_ssim(const float* __restrict__ img1, const float* __restrict__ img2,
            float* __restrict__ out) {
    __shared__ u64   s01[TILE_H][SROW];   // packed (vconv img1, vconv img2)
    __shared__ u64   s23[TILE_H][SROW];   // packed (vconv img1^2, vconv img2^2)
    __shared__ float s4 [TILE_H][SROW];   // vconv img1*img2
    __shared__ float warpsum[4];
    __shared__ int   s_last;
    __shared__ double red[4];

    // scalar weights as literals (FFMA-imm, rt=1)
    const float Wf[11] = {W0, W1, W2, W3, W4, W5, W4, W3, W2, W1, W0};
    // packed weights: 6 distinct by symmetry
    u64 w2[6];
    {
        const float wv[6] = {W0, W1, W2, W3, W4, W5};
#pragma unroll
        for (int k = 0; k < 6; k++) PACK2(w2[k], wv[k], wv[k]);
    }
#define WIDX(k) ((k) < 6 ? (k) : 10 - (k))

    const int tid = threadIdx.x;
    const int bx = blockIdx.x, by = blockIdx.y, z = blockIdx.z;
    const float* p1 = img1 + (size_t)z * IMG * IMG;
    const float* p2 = img2 + (size_t)z * IMG * IMG;
    const int ybase = by * TILE_H;

    // ---------------- Phase 1: vertical 11-tap conv (warps 0-2 only; warp 3 skips) --------
    if (tid < VCOLS) {
        const int gx = bx * TILE_W + tid;
        const bool colok = (gx < IMG);

        u64 acc01[TILE_H], acc23[TILE_H];
        float acc4[TILE_H];
#pragma unroll
        for (int r = 0; r < TILE_H; r++) { acc01[r] = 0ull; acc23[r] = 0ull; acc4[r] = 0.0f; }

#pragma unroll
        for (int j = 0; j < TILE_H + 10; j++) {
            const int yin = ybase + j;
            float a = 0.0f, b = 0.0f;
            if (colok && yin < IMG) {
                a = p1[yin * IMG + gx];
                b = p2[yin * IMG + gx];
            }
            u64 vab, vsq;
            PACK2(vab, a, b);
            MUL2(vsq, vab, vab);
            const float ab = a * b;
#pragma unroll
            for (int r = 0; r < TILE_H; r++) {
                const int k = j - r;
                if (k >= 0 && k < 11) {
                    FMA2(acc01[r], vab, w2[WIDX(k)], acc01[r]);
                    FMA2(acc23[r], vsq, w2[WIDX(k)], acc23[r]);
                    acc4[r] = fmaf(Wf[k], ab, acc4[r]);
                }
            }
        }

#pragma unroll
        for (int r = 0; r < TILE_H; r++) {
            s01[r][tid] = acc01[r];
            s23[r][tid] = acc23[r];
            s4 [r][tid] = acc4[r];
        }
    }
    __syncthreads();

    // ---------------- Phase 2: horizontal 11-tap conv, 11 outputs per thread --------------
    const int y  = tid & 15;      // 0..15 output row
    const int cg = tid >> 4;      // 0..7  column group
    const int xs = cg * G;        // local out cols xs..xs+10 (reads to xs+20 <= 97 < SROW)

    u64 o01[G], o23[G];
    float o4[G];
#pragma unroll
    for (int s = 0; s < G; s++) { o01[s] = 0ull; o23[s] = 0ull; o4[s] = 0.0f; }

    {
        const u64* r01 = &s01[y][xs];
#pragma unroll
        for (int i = 0; i < 21; i++) {
            const u64 v = r01[i];
#pragma unroll
            for (int s = 0; s < G; s++) {
                const int k = i - s;
                if (k >= 0 && k < 11) FMA2(o01[s], v, w2[WIDX(k)], o01[s]);
            }
        }
    }
    {
        const u64* r23 = &s23[y][xs];
#pragma unroll
        for (int i = 0; i < 21; i++) {
            const u64 v = r23[i];
#pragma unroll
            for (int s = 0; s < G; s++) {
                const int k = i - s;
                if (k >= 0 && k < 11) FMA2(o23[s], v, w2[WIDX(k)], o23[s]);
            }
        }
    }
    {
        const float* r4 = &s4[y][xs];
#pragma unroll
        for (int i = 0; i < 21; i++) {
            const float v = r4[i];
#pragma unroll
            for (int s = 0; s < G; s++) {
                const int k = i - s;
                if (k >= 0 && k < 11) o4[s] = fmaf(Wf[k], v, o4[s]);
            }
        }
    }

    // ---------------- SSIM map + block-local sum ----------------
    const float maxv = g_flags[0] ? 255.0f : 1.0f;
    const float minv = g_flags[1] ? -1.0f : 0.0f;
    const float L  = maxv - minv;
    const float C1 = (0.01f * L) * (0.01f * L);
    const float C2 = (0.03f * L) * (0.03f * L);

    const int gy   = ybase + y;
    const int xlim = min(TILE_W, OUTD - bx * TILE_W);

    float lsum = 0.0f;
    if (gy < OUTD) {
#pragma unroll
        for (int s = 0; s < G; s++) {
            const int x = xs + s;
            if (x < xlim) {
                float mu1, mu2, e11, e22;
                UNPACK2(mu1, mu2, o01[s]);
                UNPACK2(e11, e22, o23[s]);
                const float mu1s = mu1 * mu1, mu2s = mu2 * mu2, mu12 = mu1 * mu2;
                const float s1  = e11 - mu1s;
                const float s2  = e22 - mu2s;
                const float s12 = o4[s] - mu12;
                const float num = (2.0f * mu12 + C1) * (2.0f * s12 + C2);
                const float den = (mu1s + mu2s + C1) * (s1 + s2 + C2);
                lsum += __fdividef(num, den);
            }
        }
    }

#pragma unroll
    for (int off = 16; off > 0; off >>= 1)
        lsum += __shfl_down_sync(0xffffffffu, lsum, off);

    if ((tid & 31) == 0) warpsum[tid >> 5] = lsum;
    __syncthreads();

    const int bid = bx + GBX * (by + GBY * z);
    if (tid == 0) {
        g_partials[bid] = warpsum[0] + warpsum[1] + warpsum[2] + warpsum[3];
        __threadfence();
        unsigned v = atomicAdd(&g_count, 1u);
        s_last = (v == NBLK - 1) ? 1 : 0;
    }
    __syncthreads();

    // ---------------- last block: final reduction + state reset ----------------
    if (s_last) {
        double s = 0.0;
        const int per = NBLK / 128;  // 144
#pragma unroll 4
        for (int i = 0; i < per; i++)
            s += (double)__ldcg(&g_partials[tid * per + i]);
#pragma unroll
        for (int off = 16; off > 0; off >>= 1)
            s += __shfl_down_sync(0xffffffffu, s, off);
        if ((tid & 31) == 0) red[tid >> 5] = s;
        __syncthreads();
        if (tid == 0) {
            const double cnt = (double)NIMG * OUTD * OUTD;
            out[0] = (float)(1.0 - (red[0] + red[1] + red[2] + red[3]) / cnt);
            g_flags[0] = 0;
            g_flags[1] = 0;
            g_count    = 0u;
        }
    }
}

extern "C" void kernel_launch(void* const* d_in, const int* in_sizes, int n_in,
                              void* d_out, int out_size) {
    const float* img1 = (const float*)d_in[0];
    const float* img2 = (const float*)d_in[1];
    float* out = (float*)d_out;

    k_flags<<<2048, 256>>>((const float4*)img1, (IMG * IMG * NIMG) / 4);
    dim3 grid(GBX, GBY, NIMG);
    k_ssim<<<grid, 128>>>(img1, img2, out);
}